// round 11
// baseline (speedup 1.0000x reference)
#include <cuda_runtime.h>

constexpr int D  = 128;   // D_IN
constexpr int C  = 64;    // NUM_CLASSES
constexpr int E  = 64;    // D_OUT
constexpr int G1 = 148;
constexpr int TPB = 384;  // 12 warps
constexpr int GROUPS = 6; // 2 warps per group, one 32KB replica each
constexpr int U  = 8;     // rows per group per iteration
constexpr int ROWS_ITER = GROUPS * U;  // 48 rows / block / iter

// Zero-initialized scratch; launch self-cleans for graph replays.
__device__ float    g_sumS[C * D];
__device__ int      g_cnt[C];
__device__ unsigned g_count   = 0;
__device__ unsigned g_release = 0;

__global__ __launch_bounds__(TPB, 1)
void fused_kernel(const float* __restrict__ x,
                  const int*   __restrict__ labels,
                  const float* __restrict__ W,
                  const float* __restrict__ bias,
                  float*       __restrict__ out,
                  int n) {
    extern __shared__ float sm[];
    float* acc_all = sm;                       // GROUPS*C*D floats (192 KB)
    __shared__ int      shist[C];
    __shared__ unsigned rel0;

    const int tid  = threadIdx.x;
    const int grp  = tid >> 6;                 // 0..5
    const int col2 = (tid & 63) * 2;           // owned column pair
    float* acc = acc_all + grp * (C * D);

    if (tid == 0) rel0 = *(volatile unsigned*)&g_release;
    for (int i = tid; i < GROUPS * C * D; i += TPB) acc_all[i] = 0.f;
    if (tid < C) shist[tid] = 0;
    __syncthreads();

    const int g = gridDim.x;
    const int chunk = ((n + g * ROWS_ITER - 1) / (g * ROWS_ITER)) * ROWS_ITER;
    const int r0 = blockIdx.x * chunk;
    const int r1 = min(n, r0 + chunk);
    const int nfull = max(0, r1 - r0) / ROWS_ITER;

    for (int it = 0; it < nfull; it++) {
        const int base = r0 + it * ROWS_ITER + grp * U;

        int lab[U];
        {
            const int4* lp = (const int4*)(labels + base);
            int4 a = lp[0], b = lp[1];
            lab[0]=a.x; lab[1]=a.y; lab[2]=a.z; lab[3]=a.w;
            lab[4]=b.x; lab[5]=b.y; lab[6]=b.z; lab[7]=b.w;
        }

        float2 v[U];
        #pragma unroll
        for (int u = 0; u < U; u++)
            v[u] = *(const float2*)(x + (size_t)(base + u) * D + col2);

        // dup bitmask: dup[u] = label seen earlier in this batch
        unsigned long long seen = 0; unsigned dupm = 0;
        #pragma unroll
        for (int u = 0; u < U; u++) {
            unsigned long long b = 1ull << lab[u];
            dupm |= (seen & b) ? (1u << u) : 0u;
            seen |= b;
        }

        int ad[U];
        #pragma unroll
        for (int u = 0; u < U; u++) ad[u] = lab[u] * D + col2;

        // batched phase: ALL loads first (latencies overlap; first
        // occurrences have pairwise-distinct addresses), then add+store
        float2 cur[U];
        #pragma unroll
        for (int u = 0; u < U; u++)
            cur[u] = *(const float2*)&acc[ad[u]];
        #pragma unroll
        for (int u = 0; u < U; u++) {
            if (!((dupm >> u) & 1u)) {
                cur[u].x += v[u].x; cur[u].y += v[u].y;
                *(float2*)&acc[ad[u]] = cur[u];
            }
        }
        // rare dup rows: serial RMW (program order puts this after the STS)
        if (dupm) {
            #pragma unroll
            for (int u = 0; u < U; u++) {
                if ((dupm >> u) & 1u) {
                    float2 t = *(const float2*)&acc[ad[u]];
                    t.x += v[u].x; t.y += v[u].y;
                    *(float2*)&acc[ad[u]] = t;
                }
            }
        }
    }

    // tail rows (group 0 only)
    if (grp == 0) {
        for (int m = r0 + nfull * ROWS_ITER; m < r1; m++) {
            int lb = labels[m];
            float2* a = (float2*)&acc[lb * D + col2];
            float2 c = *a;
            c.x += x[(size_t)m * D + col2];
            c.y += x[(size_t)m * D + col2 + 1];
            *a = c;
        }
    }

    // counts: separate histogram pass over this block's labels (~4MB total)
    for (int m = r0 + tid; m < r1; m += TPB)
        atomicAdd_block(&shist[labels[m]], 1);
    __syncthreads();

    // merge replicas -> global accumulator (REDG, no return)
    for (int i = tid; i < C * D; i += TPB) {
        float s = 0.f;
        #pragma unroll
        for (int gg = 0; gg < GROUPS; gg++) s += acc_all[gg * C * D + i];
        atomicAdd(&g_sumS[i], s);
    }
    if (tid < C && shist[tid]) atomicAdd(&g_cnt[tid], shist[tid]);

    // ---- replay-safe software grid barrier ----
    __threadfence();
    __syncthreads();
    if (tid == 0) {
        unsigned arrived = atomicAdd(&g_count, 1) + 1;
        if (arrived == (unsigned)gridDim.x) {
            g_count = 0;
            __threadfence();
            atomicAdd(&g_release, 1u);
        }
        while (*(volatile unsigned*)&g_release == rel0) __nanosleep(32);
    }
    __syncthreads();
    __threadfence();

    // ---- epilogue: per-class GEMM + divide, then self-clean ----
    for (int c = blockIdx.x; c < C; c += gridDim.x) {
        __shared__ float Srow[D];
        __shared__ float cntf;
        if (tid < D) Srow[tid] = __ldcg(&g_sumS[c * D + tid]);
        if (tid == 0) cntf = (float)__ldcg(&g_cnt[c]);
        __syncthreads();

        if (tid < E) {
            float a = 0.f;
            #pragma unroll
            for (int dd = 0; dd < D; dd++)
                a += Srow[dd] * __ldg(&W[dd * E + tid]);
            float ct = cntf;
            out[c * E + tid] = (a + ct * bias[tid]) / fmaxf(ct, 1.f);
        }
        __syncthreads();
        if (tid < D) g_sumS[c * D + tid] = 0.f;
        if (tid == 0) g_cnt[c] = 0;
        __syncthreads();
    }
}

extern "C" void kernel_launch(void* const* d_in, const int* in_sizes, int n_in,
                              void* d_out, int out_size) {
    const float* x      = (const float*)d_in[0];   // [N, 128] f32
    const int*   labels = (const int*)d_in[1];     // [N] i32
    const float* W      = (const float*)d_in[2];   // [128, 64] f32
    const float* bias   = (const float*)d_in[3];   // [64] f32
    float* out = (float*)d_out;                    // [64, 64] f32

    const int n = in_sizes[1];

    const size_t smem1 = (size_t)GROUPS * C * D * sizeof(float); // 196,608 B
    cudaFuncSetAttribute(fused_kernel,
                         cudaFuncAttributeMaxDynamicSharedMemorySize,
                         (int)smem1);

    // Residency safety for the software grid barrier
    int dev = 0, numSM = 148, maxPerSM = 1;
    cudaGetDevice(&dev);
    cudaDeviceGetAttribute(&numSM, cudaDevAttrMultiProcessorCount, dev);
    cudaOccupancyMaxActiveBlocksPerMultiprocessor(&maxPerSM, fused_kernel,
                                                  TPB, smem1);
    int grid = numSM * (maxPerSM > 0 ? maxPerSM : 1);
    if (grid > G1) grid = G1;

    fused_kernel<<<grid, TPB, smem1>>>(x, labels, W, bias, out, n);
}

// round 12
// speedup vs baseline: 1.0085x; 1.0085x over previous
#include <cuda_runtime.h>

constexpr int D  = 128;   // D_IN
constexpr int C  = 64;    // NUM_CLASSES
constexpr int E  = 64;    // D_OUT
constexpr int G1 = 148;
constexpr int TPB = 384;  // 12 warps
constexpr int GROUPS = 6; // 2 warps per group, one 32KB replica each
constexpr int U  = 8;     // rows per group per iteration
constexpr int ROWS_ITER = GROUPS * U;  // 48 rows / block / iter

// Zero-initialized scratch; launch self-cleans for graph replays.
__device__ float    g_sumS[C * D];
__device__ int      g_cnt[C];
__device__ unsigned g_count   = 0;
__device__ unsigned g_release = 0;

__global__ __launch_bounds__(TPB, 1)
void fused_kernel(const float* __restrict__ x,
                  const int*   __restrict__ labels,
                  const float* __restrict__ W,
                  const float* __restrict__ bias,
                  float*       __restrict__ out,
                  int n) {
    extern __shared__ float sm[];
    float* acc_all = sm;                       // GROUPS*C*D floats (192 KB)
    __shared__ int      shist[C];
    __shared__ unsigned rel0;

    const int tid  = threadIdx.x;
    const int grp  = tid >> 6;                 // 0..5
    const int col2 = (tid & 63) * 2;           // owned column pair
    float* acc = acc_all + grp * (C * D);

    if (tid == 0) rel0 = *(volatile unsigned*)&g_release;
    for (int i = tid; i < GROUPS * C * D; i += TPB) acc_all[i] = 0.f;
    if (tid < C) shist[tid] = 0;
    __syncthreads();

    const int g = gridDim.x;
    const int chunk = ((n + g * ROWS_ITER - 1) / (g * ROWS_ITER)) * ROWS_ITER;
    const int r0 = blockIdx.x * chunk;
    const int r1 = min(n, r0 + chunk);
    const int nfull = max(0, r1 - r0) / ROWS_ITER;

    for (int it = 0; it < nfull; it++) {
        const int base = r0 + it * ROWS_ITER + grp * U;

        int lab[U];
        {
            const int4* lp = (const int4*)(labels + base);
            int4 a = lp[0], b = lp[1];
            lab[0]=a.x; lab[1]=a.y; lab[2]=a.z; lab[3]=a.w;
            lab[4]=b.x; lab[5]=b.y; lab[6]=b.z; lab[7]=b.w;
        }

        float2 v[U];
        #pragma unroll
        for (int u = 0; u < U; u++)
            v[u] = *(const float2*)(x + (size_t)(base + u) * D + col2);

        // dup bitmask: dup[u] = label seen earlier in this batch
        unsigned long long seen = 0; unsigned dupm = 0;
        #pragma unroll
        for (int u = 0; u < U; u++) {
            unsigned long long b = 1ull << lab[u];
            dupm |= (seen & b) ? (1u << u) : 0u;
            seen |= b;
        }

        int ad[U];
        #pragma unroll
        for (int u = 0; u < U; u++) ad[u] = lab[u] * D + col2;

        // batched phase: ALL loads first (latencies overlap; first
        // occurrences have pairwise-distinct addresses), then add+store
        float2 cur[U];
        #pragma unroll
        for (int u = 0; u < U; u++)
            cur[u] = *(const float2*)&acc[ad[u]];
        #pragma unroll
        for (int u = 0; u < U; u++) {
            if (!((dupm >> u) & 1u)) {
                cur[u].x += v[u].x; cur[u].y += v[u].y;
                *(float2*)&acc[ad[u]] = cur[u];
            }
        }
        // rare dup rows: serial RMW (program order puts this after the STS)
        if (dupm) {
            #pragma unroll
            for (int u = 0; u < U; u++) {
                if ((dupm >> u) & 1u) {
                    float2 t = *(const float2*)&acc[ad[u]];
                    t.x += v[u].x; t.y += v[u].y;
                    *(float2*)&acc[ad[u]] = t;
                }
            }
        }
    }

    // tail rows (group 0 only)
    if (grp == 0) {
        for (int m = r0 + nfull * ROWS_ITER; m < r1; m++) {
            int lb = labels[m];
            float2* a = (float2*)&acc[lb * D + col2];
            float2 c = *a;
            c.x += x[(size_t)m * D + col2];
            c.y += x[(size_t)m * D + col2 + 1];
            *a = c;
        }
    }

    // counts: separate histogram pass over this block's labels (~4MB total)
    for (int m = r0 + tid; m < r1; m += TPB)
        atomicAdd_block(&shist[labels[m]], 1);
    __syncthreads();

    // merge replicas -> global accumulator (REDG, no return)
    for (int i = tid; i < C * D; i += TPB) {
        float s = 0.f;
        #pragma unroll
        for (int gg = 0; gg < GROUPS; gg++) s += acc_all[gg * C * D + i];
        atomicAdd(&g_sumS[i], s);
    }
    if (tid < C && shist[tid]) atomicAdd(&g_cnt[tid], shist[tid]);

    // ---- replay-safe software grid barrier ----
    __threadfence();
    __syncthreads();
    if (tid == 0) {
        unsigned arrived = atomicAdd(&g_count, 1) + 1;
        if (arrived == (unsigned)gridDim.x) {
            g_count = 0;
            __threadfence();
            atomicAdd(&g_release, 1u);
        }
        while (*(volatile unsigned*)&g_release == rel0) __nanosleep(32);
    }
    __syncthreads();
    __threadfence();

    // ---- epilogue: per-class GEMM + divide, then self-clean ----
    for (int c = blockIdx.x; c < C; c += gridDim.x) {
        __shared__ float Srow[D];
        __shared__ float cntf;
        if (tid < D) Srow[tid] = __ldcg(&g_sumS[c * D + tid]);
        if (tid == 0) cntf = (float)__ldcg(&g_cnt[c]);
        __syncthreads();

        if (tid < E) {
            float a = 0.f;
            #pragma unroll
            for (int dd = 0; dd < D; dd++)
                a += Srow[dd] * __ldg(&W[dd * E + tid]);
            float ct = cntf;
            out[c * E + tid] = (a + ct * bias[tid]) / fmaxf(ct, 1.f);
        }
        __syncthreads();
        if (tid < D) g_sumS[c * D + tid] = 0.f;
        if (tid == 0) g_cnt[c] = 0;
        __syncthreads();
    }
}

extern "C" void kernel_launch(void* const* d_in, const int* in_sizes, int n_in,
                              void* d_out, int out_size) {
    const float* x      = (const float*)d_in[0];   // [N, 128] f32
    const int*   labels = (const int*)d_in[1];     // [N] i32
    const float* W      = (const float*)d_in[2];   // [128, 64] f32
    const float* bias   = (const float*)d_in[3];   // [64] f32
    float* out = (float*)d_out;                    // [64, 64] f32

    const int n = in_sizes[1];

    const size_t smem1 = (size_t)GROUPS * C * D * sizeof(float); // 196,608 B
    cudaFuncSetAttribute(fused_kernel,
                         cudaFuncAttributeMaxDynamicSharedMemorySize,
                         (int)smem1);

    // Residency safety for the software grid barrier
    int dev = 0, numSM = 148, maxPerSM = 1;
    cudaGetDevice(&dev);
    cudaDeviceGetAttribute(&numSM, cudaDevAttrMultiProcessorCount, dev);
    cudaOccupancyMaxActiveBlocksPerMultiprocessor(&maxPerSM, fused_kernel,
                                                  TPB, smem1);
    int grid = numSM * (maxPerSM > 0 ? maxPerSM : 1);
    if (grid > G1) grid = G1;

    fused_kernel<<<grid, TPB, smem1>>>(x, labels, W, bias, out, n);
}

// round 13
// speedup vs baseline: 1.0132x; 1.0047x over previous
#include <cuda_runtime.h>

constexpr int D  = 128;   // D_IN
constexpr int C  = 64;    // NUM_CLASSES
constexpr int E  = 64;    // D_OUT
constexpr int G1 = 148;
constexpr int TPB = 384;  // 12 warps
constexpr int GROUPS = 6; // 2 warps per group, one 32KB replica each
constexpr int U  = 8;     // rows per group per iteration
constexpr int ROWS_ITER = GROUPS * U;  // 48 rows / block / iter

// Zero-initialized scratch; launch self-cleans for graph replays.
__device__ float    g_sumS[C * D];
__device__ int      g_cnt[C];
__device__ unsigned g_count   = 0;
__device__ unsigned g_release = 0;

__global__ __launch_bounds__(TPB, 1)
void fused_kernel(const float* __restrict__ x,
                  const int*   __restrict__ labels,
                  const float* __restrict__ W,
                  const float* __restrict__ bias,
                  float*       __restrict__ out,
                  int n) {
    extern __shared__ float sm[];
    float* acc_all = sm;                       // GROUPS*C*D floats (192 KB)
    __shared__ int      shist[C];
    __shared__ unsigned rel0;

    const int tid  = threadIdx.x;
    const int grp  = tid >> 6;                 // 0..5
    const int col2 = (tid & 63) * 2;           // owned column pair
    float* acc = acc_all + grp * (C * D);

    if (tid == 0) rel0 = *(volatile unsigned*)&g_release;
    for (int i = tid; i < GROUPS * C * D; i += TPB) acc_all[i] = 0.f;
    if (tid < C) shist[tid] = 0;
    __syncthreads();

    const int g = gridDim.x;
    const int chunk = ((n + g * ROWS_ITER - 1) / (g * ROWS_ITER)) * ROWS_ITER;
    const int r0 = blockIdx.x * chunk;
    const int r1 = min(n, r0 + chunk);
    const int nfull = max(0, r1 - r0) / ROWS_ITER;

    for (int it = 0; it < nfull; it++) {
        const int base = r0 + it * ROWS_ITER + grp * U;

        int lab[U];
        {
            const int4* lp = (const int4*)(labels + base);
            int4 a = lp[0], b = lp[1];
            lab[0]=a.x; lab[1]=a.y; lab[2]=a.z; lab[3]=a.w;
            lab[4]=b.x; lab[5]=b.y; lab[6]=b.z; lab[7]=b.w;
        }

        float2 v[U];
        #pragma unroll
        for (int u = 0; u < U; u++)
            v[u] = *(const float2*)(x + (size_t)(base + u) * D + col2);

        // dup bitmask: dup[u] = label seen earlier in this batch
        unsigned long long seen = 0; unsigned dupm = 0;
        #pragma unroll
        for (int u = 0; u < U; u++) {
            unsigned long long b = 1ull << lab[u];
            dupm |= (seen & b) ? (1u << u) : 0u;
            seen |= b;
        }

        int ad[U];
        #pragma unroll
        for (int u = 0; u < U; u++) ad[u] = lab[u] * D + col2;

        // batched phase: ALL loads first (latencies overlap; first
        // occurrences have pairwise-distinct addresses), then add+store
        float2 cur[U];
        #pragma unroll
        for (int u = 0; u < U; u++)
            cur[u] = *(const float2*)&acc[ad[u]];
        #pragma unroll
        for (int u = 0; u < U; u++) {
            if (!((dupm >> u) & 1u)) {
                cur[u].x += v[u].x; cur[u].y += v[u].y;
                *(float2*)&acc[ad[u]] = cur[u];
            }
        }
        // rare dup rows: serial RMW (program order puts this after the STS)
        if (dupm) {
            #pragma unroll
            for (int u = 0; u < U; u++) {
                if ((dupm >> u) & 1u) {
                    float2 t = *(const float2*)&acc[ad[u]];
                    t.x += v[u].x; t.y += v[u].y;
                    *(float2*)&acc[ad[u]] = t;
                }
            }
        }
    }

    // tail rows (group 0 only)
    if (grp == 0) {
        for (int m = r0 + nfull * ROWS_ITER; m < r1; m++) {
            int lb = labels[m];
            float2* a = (float2*)&acc[lb * D + col2];
            float2 c = *a;
            c.x += x[(size_t)m * D + col2];
            c.y += x[(size_t)m * D + col2 + 1];
            *a = c;
        }
    }

    // counts: separate histogram pass over this block's labels (~4MB total)
    for (int m = r0 + tid; m < r1; m += TPB)
        atomicAdd_block(&shist[labels[m]], 1);
    __syncthreads();

    // merge replicas -> global accumulator (REDG, no return)
    for (int i = tid; i < C * D; i += TPB) {
        float s = 0.f;
        #pragma unroll
        for (int gg = 0; gg < GROUPS; gg++) s += acc_all[gg * C * D + i];
        atomicAdd(&g_sumS[i], s);
    }
    if (tid < C && shist[tid]) atomicAdd(&g_cnt[tid], shist[tid]);

    // ---- replay-safe software grid barrier ----
    __threadfence();
    __syncthreads();
    if (tid == 0) {
        unsigned arrived = atomicAdd(&g_count, 1) + 1;
        if (arrived == (unsigned)gridDim.x) {
            g_count = 0;
            __threadfence();
            atomicAdd(&g_release, 1u);
        }
        while (*(volatile unsigned*)&g_release == rel0) __nanosleep(32);
    }
    __syncthreads();
    __threadfence();

    // ---- epilogue: per-class GEMM + divide, then self-clean ----
    for (int c = blockIdx.x; c < C; c += gridDim.x) {
        __shared__ float Srow[D];
        __shared__ float cntf;
        if (tid < D) Srow[tid] = __ldcg(&g_sumS[c * D + tid]);
        if (tid == 0) cntf = (float)__ldcg(&g_cnt[c]);
        __syncthreads();

        if (tid < E) {
            float a = 0.f;
            #pragma unroll
            for (int dd = 0; dd < D; dd++)
                a += Srow[dd] * __ldg(&W[dd * E + tid]);
            float ct = cntf;
            out[c * E + tid] = (a + ct * bias[tid]) / fmaxf(ct, 1.f);
        }
        __syncthreads();
        if (tid < D) g_sumS[c * D + tid] = 0.f;
        if (tid == 0) g_cnt[c] = 0;
        __syncthreads();
    }
}

extern "C" void kernel_launch(void* const* d_in, const int* in_sizes, int n_in,
                              void* d_out, int out_size) {
    const float* x      = (const float*)d_in[0];   // [N, 128] f32
    const int*   labels = (const int*)d_in[1];     // [N] i32
    const float* W      = (const float*)d_in[2];   // [128, 64] f32
    const float* bias   = (const float*)d_in[3];   // [64] f32
    float* out = (float*)d_out;                    // [64, 64] f32

    const int n = in_sizes[1];

    const size_t smem1 = (size_t)GROUPS * C * D * sizeof(float); // 196,608 B
    cudaFuncSetAttribute(fused_kernel,
                         cudaFuncAttributeMaxDynamicSharedMemorySize,
                         (int)smem1);

    // Residency safety for the software grid barrier
    int dev = 0, numSM = 148, maxPerSM = 1;
    cudaGetDevice(&dev);
    cudaDeviceGetAttribute(&numSM, cudaDevAttrMultiProcessorCount, dev);
    cudaOccupancyMaxActiveBlocksPerMultiprocessor(&maxPerSM, fused_kernel,
                                                  TPB, smem1);
    int grid = numSM * (maxPerSM > 0 ? maxPerSM : 1);
    if (grid > G1) grid = G1;

    fused_kernel<<<grid, TPB, smem1>>>(x, labels, W, bias, out, n);
}